// round 1
// baseline (speedup 1.0000x reference)
#include <cuda_runtime.h>
#include <math.h>

#define B_    8
#define C_    96
#define C2_   192
#define H_    128
#define W_    128
#define NPIX  16384
#define HEADS_ 6

typedef unsigned long long u64;

__device__ __forceinline__ u64 pk2(float lo, float hi) {
    u64 r; asm("mov.b64 %0,{%1,%2};" : "=l"(r) : "f"(lo), "f"(hi)); return r;
}
__device__ __forceinline__ u64 fma2(u64 a, u64 b, u64 c) {
    u64 d; asm("fma.rn.f32x2 %0,%1,%2,%3;" : "=l"(d) : "l"(a), "l"(b), "l"(c)); return d;
}
__device__ __forceinline__ void unpk(u64 a, float& lo, float& hi) {
    asm("mov.b64 {%0,%1},%2;" : "=f"(lo), "=f"(hi) : "l"(a));
}

// ---- device-global scratch (no runtime allocation allowed) ----
__device__ float g_t  [B_ * C2_ * NPIX];   // 1x1 output before depthwise
__device__ float g_qv [B_ * C2_ * NPIX];   // qv_ after dw
__device__ float g_kv [B_ * C2_ * NPIX];   // kv after dw
__device__ float g_v  [B_ * C_  * NPIX];   // fused v
__device__ float g_att[B_ * C_  * NPIX];   // attention output
__device__ float g_rq [B_ * C_];
__device__ float g_rk [B_ * C_];
__device__ float g_attn[B_ * HEADS_ * 16 * 16];
__device__ float g_wpack[C2_ * 288];       // [w_proj | w_pos] packed per row

// ======================= generic 1x1-conv GEMM =======================
// out[b, m, n] = sum_k W[m,k] * IN[b,k,n], K in multiples of 96, each
// 96-channel chunk sourced from in0/in1/in2 ([B,96,N] each).
#define GT_TN 512
#define GT_TM 32
__global__ __launch_bounds__(256, 1)
void gemm1x1_kernel(const float* __restrict__ in0, const float* __restrict__ in1,
                    const float* __restrict__ in2, const float* __restrict__ Wt,
                    float* __restrict__ out, int M, int K)
{
    extern __shared__ float sm[];
    float* sin = sm;                       // [96][GT_TN]
    u64*  sw  = (u64*)(sm + 96 * GT_TN);   // [ic][GT_TM] splatted pairs
    int tid = threadIdx.x;
    int b   = blockIdx.z;
    int mb  = blockIdx.y * GT_TM;
    int n0  = blockIdx.x * GT_TN;

    u64 acc[GT_TM];
#pragma unroll
    for (int u = 0; u < GT_TM; u++) acc[u] = 0ull;

    int nch = K / 96;
    for (int ch = 0; ch < nch; ch++) {
        const float* src = (ch == 0) ? in0 : (ch == 1) ? in1 : in2;
        const float* sb = src + (size_t)b * 96 * NPIX + n0;
        for (int idx = tid; idx < 96 * GT_TN; idx += 256) {
            int c = idx >> 9;
            int p = idx & (GT_TN - 1);
            sin[idx] = sb[(size_t)c * NPIX + p];
        }
        for (int idx = tid; idx < 96 * GT_TM; idx += 256) {
            int ic = idx >> 5, u = idx & 31;
            float w = Wt[(size_t)(mb + u) * K + ch * 96 + ic];
            sw[idx] = pk2(w, w);
        }
        __syncthreads();
        const u64* sp = (const u64*)sin;
#pragma unroll 2
        for (int ic = 0; ic < 96; ic++) {
            u64 xv = sp[ic * (GT_TN / 2) + tid];
            const ulonglong2* wr = (const ulonglong2*)(sw + ic * GT_TM);
#pragma unroll
            for (int u = 0; u < GT_TM; u += 2) {
                ulonglong2 w2 = wr[u >> 1];
                acc[u]     = fma2(w2.x, xv, acc[u]);
                acc[u + 1] = fma2(w2.y, xv, acc[u + 1]);
            }
        }
        __syncthreads();
    }
#pragma unroll
    for (int u = 0; u < GT_TM; u++) {
        float lo, hi; unpk(acc[u], lo, hi);
        *(float2*)(out + ((size_t)b * M + mb + u) * NPIX + n0 + 2 * tid) = make_float2(lo, hi);
    }
}

// ======================= depthwise 3x3, pad 1 =======================
__global__ void dw3x3_kernel(const float* __restrict__ in, const float* __restrict__ wdw,
                             float* __restrict__ out)
{
    int b = blockIdx.z, c = blockIdx.y;
    int n = blockIdx.x * 256 + threadIdx.x;
    int yy = n >> 7, xx = n & 127;
    const float* ip = in + ((size_t)b * C2_ + c) * NPIX;
    const float* wp = wdw + c * 9;
    float acc = 0.f;
#pragma unroll
    for (int ky = 0; ky < 3; ky++) {
        int gy = yy + ky - 1;
        if ((unsigned)gy < 128u) {
#pragma unroll
            for (int kx = 0; kx < 3; kx++) {
                int gx = xx + kx - 1;
                if ((unsigned)gx < 128u) acc = fmaf(wp[ky * 3 + kx], ip[gy * 128 + gx], acc);
            }
        }
    }
    out[((size_t)b * C2_ + c) * NPIX + n] = acc;
}

// ======================= fuse conv 3x3: 192 -> 96 =======================
// input channel ic<96 -> kv[b, 96+ic], else qv[b, ic]
#define FZ_TR 4
#define FZ_ICC 32
#define FZ_TM 32
__global__ __launch_bounds__(256, 1)
void fuse3x3_kernel(const float* __restrict__ wf, const float* __restrict__ bias)
{
    extern __shared__ float sm[];
    float* sin = sm;                               // [32][6][132]
    u64*  sw  = (u64*)(sm + FZ_ICC * 6 * 132);     // [(ic*9+t)][32]
    int tid = threadIdx.x;
    int b   = blockIdx.z;
    int ocb = blockIdx.y * FZ_TM;
    int r0  = blockIdx.x * FZ_TR;
    int pr  = tid >> 6;             // output row within tile (0..3)
    int x0  = (tid & 63) * 2;       // output col pair start

    u64 acc[FZ_TM];
#pragma unroll
    for (int u = 0; u < FZ_TM; u++) acc[u] = 0ull;

    for (int icc = 0; icc < 6; icc++) {
        for (int idx = tid; idx < FZ_ICC * 6 * 132; idx += 256) {
            int c = idx / (6 * 132);
            int rem = idx - c * (6 * 132);
            int rr = rem / 132, cc = rem - rr * 132;
            int gy = r0 + rr - 1, gx = cc - 1;
            float v = 0.f;
            if ((unsigned)gy < 128u && (unsigned)gx < 128u) {
                int icg = icc * 32 + c;
                const float* src = (icg < 96)
                    ? (g_kv + ((size_t)b * C2_ + 96 + icg) * NPIX)
                    : (g_qv + ((size_t)b * C2_ + icg) * NPIX);
                v = src[gy * 128 + gx];
            }
            sin[idx] = v;
        }
        for (int idx = tid; idx < FZ_TM * FZ_ICC * 9; idx += 256) {
            int u = idx & 31;
            int r = idx >> 5;            // ic*9 + t
            int ic = r / 9, t = r - ic * 9;
            float w = wf[(((size_t)(ocb + u) * C2_) + icc * 32 + ic) * 9 + t];
            sw[idx] = pk2(w, w);
        }
        __syncthreads();
        for (int ic = 0; ic < FZ_ICC; ic++) {
#pragma unroll
            for (int t = 0; t < 9; t++) {
                int ky = t / 3, kx = t - ky * 3;
                int base = (ic * 6 + pr + ky) * 132 + x0 + kx;
                u64 xv = pk2(sin[base], sin[base + 1]);
                const ulonglong2* wr = (const ulonglong2*)(sw + (ic * 9 + t) * 32);
#pragma unroll
                for (int u = 0; u < FZ_TM; u += 2) {
                    ulonglong2 w2 = wr[u >> 1];
                    acc[u]     = fma2(w2.x, xv, acc[u]);
                    acc[u + 1] = fma2(w2.y, xv, acc[u + 1]);
                }
            }
        }
        __syncthreads();
    }
    int yy = r0 + pr;
#pragma unroll
    for (int u = 0; u < FZ_TM; u++) {
        float bv = bias[ocb + u];
        float lo, hi; unpk(acc[u], lo, hi);
        *(float2*)(g_v + ((size_t)b * C_ + ocb + u) * NPIX + yy * 128 + x0)
            = make_float2(lo + bv, hi + bv);
    }
}

// ======================= L2 norms of q, k rows =======================
__global__ void norm_kernel()
{
    __shared__ float red[256];
    int c = blockIdx.x, b = blockIdx.y, which = blockIdx.z;
    const float* src = (which ? g_kv : g_qv) + ((size_t)b * C2_ + c) * NPIX;
    float ss = 0.f;
    for (int n = threadIdx.x; n < NPIX; n += 256) { float v = src[n]; ss = fmaf(v, v, ss); }
    red[threadIdx.x] = ss;
    __syncthreads();
    for (int s = 128; s > 0; s >>= 1) {
        if (threadIdx.x < s) red[threadIdx.x] += red[threadIdx.x + s];
        __syncthreads();
    }
    if (threadIdx.x == 0) {
        float inv = 1.f / fmaxf(sqrtf(red[0]), 1e-12f);
        (which ? g_rk : g_rq)[b * C_ + c] = inv;
    }
}

// =============== 16x16 gram + temperature + softmax per (b,h) ===============
#define GR_NC 256
__global__ void attn_kernel(const float* __restrict__ temp)
{
    __shared__ float sq[16][GR_NC + 2];
    __shared__ float sk[16][GR_NC + 2];
    __shared__ float gm[16][17];
    int h = blockIdx.x, b = blockIdx.y;
    int tid = threadIdx.x;
    int i = tid >> 4, j = tid & 15;
    const float* qb = g_qv + ((size_t)b * C2_ + h * 16) * NPIX;
    const float* kb = g_kv + ((size_t)b * C2_ + h * 16) * NPIX;
    float acc = 0.f;
    for (int n0 = 0; n0 < NPIX; n0 += GR_NC) {
        for (int idx = tid; idx < 16 * GR_NC; idx += 256) {
            int c = idx >> 8, nn = idx & (GR_NC - 1);
            sq[c][nn] = qb[(size_t)c * NPIX + n0 + nn];
            sk[c][nn] = kb[(size_t)c * NPIX + n0 + nn];
        }
        __syncthreads();
#pragma unroll 4
        for (int nn = 0; nn < GR_NC; nn++) acc = fmaf(sq[i][nn], sk[j][nn], acc);
        __syncthreads();
    }
    gm[i][j] = acc * g_rq[b * C_ + h * 16 + i] * g_rk[b * C_ + h * 16 + j] * temp[h];
    __syncthreads();
    if (tid < 16) {
        int ii = tid;
        float m = -1e30f;
        for (int jj = 0; jj < 16; jj++) m = fmaxf(m, gm[ii][jj]);
        float e[16], s = 0.f;
        for (int jj = 0; jj < 16; jj++) { e[jj] = expf(gm[ii][jj] - m); s += e[jj]; }
        float inv = 1.f / s;
        for (int jj = 0; jj < 16; jj++)
            g_attn[(((size_t)b * HEADS_ + h) * 16 + ii) * 16 + jj] = e[jj] * inv;
    }
}

// ================== out[b,c,n] = sum_j attn[b,h,i,j] * v[b,h*16+j,n] ==================
#define AP_TN 512
__global__ __launch_bounds__(256, 1)
void applyattn_kernel()
{
    extern __shared__ float sm[];
    float* sv = sm;                       // [96][AP_TN]
    float* sa = sm + 96 * AP_TN;          // [1536]
    int tid = threadIdx.x;
    int b = blockIdx.y;
    int n0 = blockIdx.x * AP_TN;
    for (int idx = tid; idx < 96 * AP_TN; idx += 256) {
        int c = idx >> 9, pp = idx & (AP_TN - 1);
        sv[idx] = g_v[((size_t)b * C_ + c) * NPIX + n0 + pp];
    }
    for (int idx = tid; idx < 1536; idx += 256) sa[idx] = g_attn[(size_t)b * 1536 + idx];
    __syncthreads();
    const u64* svp = (const u64*)sv;
    for (int c = 0; c < C_; c++) {
        int hh = c >> 4, ii = c & 15;
        u64 acc = 0ull;
        const float* ar = sa + (hh * 16 + ii) * 16;
#pragma unroll
        for (int jj = 0; jj < 16; jj++) {
            float a = ar[jj];
            acc = fma2(pk2(a, a), svp[(hh * 16 + jj) * (AP_TN / 2) + tid], acc);
        }
        float lo, hi; unpk(acc, lo, hi);
        *(float2*)(g_att + ((size_t)b * C_ + c) * NPIX + n0 + 2 * tid) = make_float2(lo, hi);
    }
}

// ================== pack [w_proj | w_pos] into one [192][288] matrix ==================
__global__ void pack_kernel(const float* __restrict__ w_proj, const float* __restrict__ w_pos)
{
    int idx = blockIdx.x * 256 + threadIdx.x;
    if (idx < C2_ * 288) {
        int oc = idx / 288, col = idx - oc * 288;
        g_wpack[idx] = (col < 96) ? w_proj[oc * 96 + col] : w_pos[oc * 192 + col - 96];
    }
}

extern "C" void kernel_launch(void* const* d_in, const int* in_sizes, int n_in,
                              void* d_out, int out_size)
{
    const float* x        = (const float*)d_in[0];
    const float* y        = (const float*)d_in[1];
    const float* w_pos    = (const float*)d_in[2];
    const float* w_qv     = (const float*)d_in[3];
    const float* w_qv_dw  = (const float*)d_in[4];
    const float* w_kv     = (const float*)d_in[5];
    const float* w_kv_dw  = (const float*)d_in[6];
    const float* w_proj   = (const float*)d_in[7];
    const float* w_fuse   = (const float*)d_in[8];
    const float* b_fuse   = (const float*)d_in[9];
    const float* temp     = (const float*)d_in[10];
    float* out = (float*)d_out;

    void *pt, *pqv, *pkv, *patt, *pwpack;
    cudaGetSymbolAddress(&pt, g_t);
    cudaGetSymbolAddress(&pqv, g_qv);
    cudaGetSymbolAddress(&pkv, g_kv);
    cudaGetSymbolAddress(&patt, g_att);
    cudaGetSymbolAddress(&pwpack, g_wpack);

    const int smem_gemm = 96 * GT_TN * 4 + GT_TM * 96 * 8;             // 221184
    const int smem_fuse = FZ_ICC * 6 * 132 * 4 + FZ_TM * FZ_ICC * 9 * 8; // 175104
    const int smem_ap   = 96 * AP_TN * 4 + 1536 * 4;                    // 202752
    cudaFuncSetAttribute(gemm1x1_kernel, cudaFuncAttributeMaxDynamicSharedMemorySize, smem_gemm);
    cudaFuncSetAttribute(fuse3x3_kernel, cudaFuncAttributeMaxDynamicSharedMemorySize, smem_fuse);
    cudaFuncSetAttribute(applyattn_kernel, cudaFuncAttributeMaxDynamicSharedMemorySize, smem_ap);

    pack_kernel<<<(C2_ * 288 + 255) / 256, 256>>>(w_proj, w_pos);

    dim3 gg(NPIX / GT_TN, C2_ / GT_TM, B_);   // (32, 6, 8)

    // qv_ branch: 1x1 then depthwise
    gemm1x1_kernel<<<gg, 256, smem_gemm>>>(x, nullptr, nullptr, w_qv, (float*)pt, C2_, 96);
    dw3x3_kernel<<<dim3(NPIX / 256, C2_, B_), 256>>>((const float*)pt, w_qv_dw, (float*)pqv);
    // kv branch
    gemm1x1_kernel<<<gg, 256, smem_gemm>>>(y, nullptr, nullptr, w_kv, (float*)pt, C2_, 96);
    dw3x3_kernel<<<dim3(NPIX / 256, C2_, B_), 256>>>((const float*)pt, w_kv_dw, (float*)pkv);
    // v = fuse3x3(cat(v0, v_)) + bias
    fuse3x3_kernel<<<dim3(H_ / FZ_TR, C_ / FZ_TM, B_), 256, smem_fuse>>>(w_fuse, b_fuse);
    // q/k L2 norms
    norm_kernel<<<dim3(C_, B_, 2), 256>>>();
    // gram + softmax
    attn_kernel<<<dim3(HEADS_, B_), 256>>>(temp);
    // out = attn @ v
    applyattn_kernel<<<dim3(NPIX / AP_TN, B_), 256, smem_ap>>>();
    // final: w_proj @ att + w_pos @ [x; y]
    gemm1x1_kernel<<<gg, 256, smem_gemm>>>((const float*)patt, x, y,
                                           (const float*)pwpack, out, C2_, 288);
}

// round 2
// speedup vs baseline: 1.5604x; 1.5604x over previous
#include <cuda_runtime.h>
#include <math.h>

#define B_    8
#define C_    96
#define C2_   192
#define H_    128
#define W_    128
#define NPIX  16384
#define HEADS_ 6

typedef unsigned long long u64;

__device__ __forceinline__ u64 pk2(float lo, float hi) {
    u64 r; asm("mov.b64 %0,{%1,%2};" : "=l"(r) : "f"(lo), "f"(hi)); return r;
}
__device__ __forceinline__ u64 fma2(u64 a, u64 b, u64 c) {
    u64 d; asm("fma.rn.f32x2 %0,%1,%2,%3;" : "=l"(d) : "l"(a), "l"(b), "l"(c)); return d;
}
__device__ __forceinline__ void unpk(u64 a, float& lo, float& hi) {
    asm("mov.b64 {%0,%1},%2;" : "=f"(lo), "=f"(hi) : "l"(a));
}

// ---- device-global scratch ----
__device__ float g_t  [B_ * C2_ * NPIX];
__device__ float g_qv [B_ * C2_ * NPIX];
__device__ float g_kv [B_ * C2_ * NPIX];
__device__ float g_v  [B_ * C_  * NPIX];
__device__ float g_att[B_ * C_  * NPIX];
__device__ float g_rq [B_ * C_];
__device__ float g_rk [B_ * C_];
__device__ float g_attn[B_ * HEADS_ * 16 * 16];
__device__ float g_wpack[C2_ * 288];

// ======================= 1x1-conv GEMM (register-tiled) =======================
// out[b,m,n] = sum_k W[m,k]*IN[k,n]. K multiple of 32; source per 96-chunk.
// Block: 32 oc x 512 px. 256 thr = 2 oc-groups x 128 px-threads.
// Thread: 16 oc x 4 px -> 32 u64 accumulators.
#define GN 512
__global__ __launch_bounds__(256, 2)
void gemm1x1_kernel(const float* __restrict__ in0, const float* __restrict__ in1,
                    const float* __restrict__ in2, const float* __restrict__ Wt,
                    float* __restrict__ out, int M, int K)
{
    extern __shared__ float sm[];
    float* sin = sm;                       // [32][512]
    u64*  sw  = (u64*)(sm + 32 * GN);      // [32 ic][32 oc] splatted
    int tid = threadIdx.x;
    int g   = tid >> 7;          // oc group (0/1)
    int p   = tid & 127;         // px thread
    int p4  = p * 4;
    int bb  = blockIdx.z;
    int mb  = blockIdx.y * 32;
    int n0  = blockIdx.x * GN;

    u64 acc[32];
#pragma unroll
    for (int u = 0; u < 32; u++) acc[u] = 0ull;

    int nch = K / 32;
    for (int ch = 0; ch < nch; ch++) {
        int k0 = ch * 32;
        const float* src = (k0 < 96) ? in0 : (k0 < 192) ? in1 : in2;
        const float* sb = src + ((size_t)bb * 96 + (k0 % 96)) * NPIX + n0;
        // stage input tile (float4)
        for (int idx = tid; idx < 32 * 128; idx += 256) {
            int c = idx >> 7, pos = idx & 127;
            ((float4*)sin)[c * 128 + pos] =
                ((const float4*)(sb + (size_t)c * NPIX))[pos];
        }
        // stage splatted weights
        for (int idx = tid; idx < 1024; idx += 256) {
            int ic = idx >> 5, oc = idx & 31;
            float w = Wt[(size_t)(mb + oc) * K + k0 + ic];
            sw[idx] = pk2(w, w);
        }
        __syncthreads();
#pragma unroll 4
        for (int ic = 0; ic < 32; ic++) {
            ulonglong2 px = *(const ulonglong2*)(sin + ic * GN + p4);
            const ulonglong2* wr = (const ulonglong2*)(sw + ic * 32 + g * 16);
#pragma unroll
            for (int jj = 0; jj < 8; jj++) {
                ulonglong2 w2 = wr[jj];
                acc[4 * jj + 0] = fma2(w2.x, px.x, acc[4 * jj + 0]);
                acc[4 * jj + 1] = fma2(w2.x, px.y, acc[4 * jj + 1]);
                acc[4 * jj + 2] = fma2(w2.y, px.x, acc[4 * jj + 2]);
                acc[4 * jj + 3] = fma2(w2.y, px.y, acc[4 * jj + 3]);
            }
        }
        __syncthreads();
    }
#pragma unroll
    for (int jj = 0; jj < 8; jj++) {
#pragma unroll
        for (int r = 0; r < 2; r++) {
            int oc = mb + g * 16 + jj * 2 + r;
            float a, b2, c2, d;
            unpk(acc[4 * jj + 2 * r], a, b2);
            unpk(acc[4 * jj + 2 * r + 1], c2, d);
            *(float4*)(out + ((size_t)bb * M + oc) * NPIX + n0 + p4) =
                make_float4(a, b2, c2, d);
        }
    }
}

// ======================= depthwise 3x3, pad 1 =======================
__global__ void dw3x3_kernel(const float* __restrict__ in, const float* __restrict__ wdw,
                             float* __restrict__ out)
{
    int b = blockIdx.z, c = blockIdx.y;
    int n = blockIdx.x * 256 + threadIdx.x;
    int yy = n >> 7, xx = n & 127;
    const float* ip = in + ((size_t)b * C2_ + c) * NPIX;
    const float* wp = wdw + c * 9;
    float acc = 0.f;
#pragma unroll
    for (int ky = 0; ky < 3; ky++) {
        int gy = yy + ky - 1;
        if ((unsigned)gy < 128u) {
#pragma unroll
            for (int kx = 0; kx < 3; kx++) {
                int gx = xx + kx - 1;
                if ((unsigned)gx < 128u) acc = fmaf(wp[ky * 3 + kx], ip[gy * 128 + gx], acc);
            }
        }
    }
    out[((size_t)b * C2_ + c) * NPIX + n] = acc;
}

// ======================= fuse conv 3x3: 192 -> 96 (register-tiled) =======================
// Block: 32 oc x (4 rows x 128 cols). 256 thr = 2 oc-groups x (4 rows x 32 col-quads).
// Thread: 16 oc x 4 px. ic chunked by 16 (12 chunks).
#define FICC 16
#define FSTR 136
__global__ __launch_bounds__(256, 2)
void fuse3x3_kernel(const float* __restrict__ wf, const float* __restrict__ bias)
{
    extern __shared__ float sm[];
    float* sin = sm;                                // [16][6][136]
    u64*  sw  = (u64*)(sm + FICC * 6 * FSTR);       // [(ic*9+t)][32] splatted
    int tid = threadIdx.x;
    int g   = tid >> 7;
    int p   = tid & 127;
    int pr  = p >> 5;            // out row in tile (0..3)
    int xq  = (p & 31) * 4;      // out col start
    int b   = blockIdx.z;
    int ocb = blockIdx.y * 32;
    int r0  = blockIdx.x * 4;

    u64 acc[32];
#pragma unroll
    for (int u = 0; u < 32; u++) acc[u] = 0ull;

    for (int ch = 0; ch < 12; ch++) {
        // stage input (16 ch x 6 rows x 136 cols, col cc -> gx = cc-1)
        for (int idx = tid; idx < FICC * 6 * FSTR; idx += 256) {
            int c = idx / (6 * FSTR);
            int rem = idx - c * (6 * FSTR);
            int rr = rem / FSTR, cc = rem - rr * FSTR;
            int gy = r0 + rr - 1, gx = cc - 1;
            float v = 0.f;
            if ((unsigned)gy < 128u && (unsigned)gx < 128u) {
                int icg = ch * FICC + c;
                const float* src = (icg < 96)
                    ? (g_kv + ((size_t)b * C2_ + 96 + icg) * NPIX)
                    : (g_qv + ((size_t)b * C2_ + icg) * NPIX);
                v = src[gy * 128 + gx];
            }
            sin[idx] = v;
        }
        // stage splatted weights: sw[(ic*9+t)*32 + oc]
        for (int idx = tid; idx < FICC * 9 * 32; idx += 256) {
            int oc = idx & 31;
            int r = idx >> 5;        // ic*9 + t
            float w = wf[(size_t)(ocb + oc) * (C2_ * 9) + ch * FICC * 9 + r];
            sw[idx] = pk2(w, w);
        }
        __syncthreads();
        for (int ic = 0; ic < FICC; ic++) {
#pragma unroll
            for (int ky = 0; ky < 3; ky++) {
                const float* rb = sin + (ic * 6 + pr + ky) * FSTR + xq;
                float4 f03 = *(const float4*)rb;
                float2 f45 = *(const float2*)(rb + 4);
                u64 pa = pk2(f03.x, f03.y);
                u64 pb = pk2(f03.z, f03.w);
                u64 pc = pk2(f03.y, f03.z);
                u64 pd = pk2(f03.w, f45.x);
                u64 pe = pk2(f45.x, f45.y);
#pragma unroll
                for (int kx = 0; kx < 3; kx++) {
                    u64 P0 = (kx == 0) ? pa : (kx == 1) ? pc : pb;
                    u64 P1 = (kx == 0) ? pb : (kx == 1) ? pd : pe;
                    const ulonglong2* wr =
                        (const ulonglong2*)(sw + (ic * 9 + ky * 3 + kx) * 32 + g * 16);
#pragma unroll
                    for (int jj = 0; jj < 8; jj++) {
                        ulonglong2 w2 = wr[jj];
                        acc[4 * jj + 0] = fma2(w2.x, P0, acc[4 * jj + 0]);
                        acc[4 * jj + 1] = fma2(w2.x, P1, acc[4 * jj + 1]);
                        acc[4 * jj + 2] = fma2(w2.y, P0, acc[4 * jj + 2]);
                        acc[4 * jj + 3] = fma2(w2.y, P1, acc[4 * jj + 3]);
                    }
                }
            }
        }
        __syncthreads();
    }
    int yy = r0 + pr;
#pragma unroll
    for (int jj = 0; jj < 8; jj++) {
#pragma unroll
        for (int r = 0; r < 2; r++) {
            int oc = ocb + g * 16 + jj * 2 + r;
            float bv = bias[oc];
            float a, b2, c2, d;
            unpk(acc[4 * jj + 2 * r], a, b2);
            unpk(acc[4 * jj + 2 * r + 1], c2, d);
            *(float4*)(g_v + ((size_t)b * C_ + oc) * NPIX + yy * 128 + xq) =
                make_float4(a + bv, b2 + bv, c2 + bv, d + bv);
        }
    }
}

// ======================= L2 norms of q, k rows =======================
__global__ void norm_kernel()
{
    __shared__ float red[256];
    int c = blockIdx.x, b = blockIdx.y, which = blockIdx.z;
    const float* src = (which ? g_kv : g_qv) + ((size_t)b * C2_ + c) * NPIX;
    float ss = 0.f;
    for (int n = threadIdx.x; n < NPIX; n += 256) { float v = src[n]; ss = fmaf(v, v, ss); }
    red[threadIdx.x] = ss;
    __syncthreads();
    for (int s = 128; s > 0; s >>= 1) {
        if (threadIdx.x < s) red[threadIdx.x] += red[threadIdx.x + s];
        __syncthreads();
    }
    if (threadIdx.x == 0) {
        float inv = 1.f / fmaxf(sqrtf(red[0]), 1e-12f);
        (which ? g_rk : g_rq)[b * C_ + c] = inv;
    }
}

// =============== 16x16 gram + temperature + softmax per (b,h) ===============
#define GR_NC 256
__global__ void attn_kernel(const float* __restrict__ temp)
{
    __shared__ float sq[16][GR_NC + 2];
    __shared__ float sk[16][GR_NC + 2];
    __shared__ float gm[16][17];
    int h = blockIdx.x, b = blockIdx.y;
    int tid = threadIdx.x;
    int i = tid >> 4, j = tid & 15;
    const float* qb = g_qv + ((size_t)b * C2_ + h * 16) * NPIX;
    const float* kb = g_kv + ((size_t)b * C2_ + h * 16) * NPIX;
    float acc = 0.f;
    for (int n0 = 0; n0 < NPIX; n0 += GR_NC) {
        for (int idx = tid; idx < 16 * GR_NC; idx += 256) {
            int c = idx >> 8, nn = idx & (GR_NC - 1);
            sq[c][nn] = qb[(size_t)c * NPIX + n0 + nn];
            sk[c][nn] = kb[(size_t)c * NPIX + n0 + nn];
        }
        __syncthreads();
#pragma unroll 4
        for (int nn = 0; nn < GR_NC; nn++) acc = fmaf(sq[i][nn], sk[j][nn], acc);
        __syncthreads();
    }
    gm[i][j] = acc * g_rq[b * C_ + h * 16 + i] * g_rk[b * C_ + h * 16 + j] * temp[h];
    __syncthreads();
    if (tid < 16) {
        int ii = tid;
        float m = -1e30f;
        for (int jj = 0; jj < 16; jj++) m = fmaxf(m, gm[ii][jj]);
        float e[16], s = 0.f;
        for (int jj = 0; jj < 16; jj++) { e[jj] = expf(gm[ii][jj] - m); s += e[jj]; }
        float inv = 1.f / s;
        for (int jj = 0; jj < 16; jj++)
            g_attn[(((size_t)b * HEADS_ + h) * 16 + ii) * 16 + jj] = e[jj] * inv;
    }
}

// ================== out[b,c,n] = sum_j attn[b,h,i,j] * v[b,h*16+j,n] ==================
#define AP_TN 512
__global__ __launch_bounds__(256, 1)
void applyattn_kernel()
{
    extern __shared__ float sm[];
    float* sv = sm;                       // [96][AP_TN]
    float* sa = sm + 96 * AP_TN;          // [1536]
    int tid = threadIdx.x;
    int b = blockIdx.y;
    int n0 = blockIdx.x * AP_TN;
    for (int idx = tid; idx < 96 * AP_TN; idx += 256) {
        int c = idx >> 9, pp = idx & (AP_TN - 1);
        sv[idx] = g_v[((size_t)b * C_ + c) * NPIX + n0 + pp];
    }
    for (int idx = tid; idx < 1536; idx += 256) sa[idx] = g_attn[(size_t)b * 1536 + idx];
    __syncthreads();
    const u64* svp = (const u64*)sv;
    for (int c = 0; c < C_; c++) {
        int hh = c >> 4, ii = c & 15;
        u64 acc = 0ull;
        const float* ar = sa + (hh * 16 + ii) * 16;
#pragma unroll
        for (int jj = 0; jj < 16; jj++) {
            float a = ar[jj];
            acc = fma2(pk2(a, a), svp[(hh * 16 + jj) * (AP_TN / 2) + tid], acc);
        }
        float lo, hi; unpk(acc, lo, hi);
        *(float2*)(g_att + ((size_t)b * C_ + c) * NPIX + n0 + 2 * tid) = make_float2(lo, hi);
    }
}

// ================== pack [w_proj | w_pos] into one [192][288] matrix ==================
__global__ void pack_kernel(const float* __restrict__ w_proj, const float* __restrict__ w_pos)
{
    int idx = blockIdx.x * 256 + threadIdx.x;
    if (idx < C2_ * 288) {
        int oc = idx / 288, col = idx - oc * 288;
        g_wpack[idx] = (col < 96) ? w_proj[oc * 96 + col] : w_pos[oc * 192 + col - 96];
    }
}

extern "C" void kernel_launch(void* const* d_in, const int* in_sizes, int n_in,
                              void* d_out, int out_size)
{
    const float* x        = (const float*)d_in[0];
    const float* y        = (const float*)d_in[1];
    const float* w_pos    = (const float*)d_in[2];
    const float* w_qv     = (const float*)d_in[3];
    const float* w_qv_dw  = (const float*)d_in[4];
    const float* w_kv     = (const float*)d_in[5];
    const float* w_kv_dw  = (const float*)d_in[6];
    const float* w_proj   = (const float*)d_in[7];
    const float* w_fuse   = (const float*)d_in[8];
    const float* b_fuse   = (const float*)d_in[9];
    const float* temp     = (const float*)d_in[10];
    float* out = (float*)d_out;

    void *pt, *pqv, *pkv, *patt, *pwpack;
    cudaGetSymbolAddress(&pt, g_t);
    cudaGetSymbolAddress(&pqv, g_qv);
    cudaGetSymbolAddress(&pkv, g_kv);
    cudaGetSymbolAddress(&patt, g_att);
    cudaGetSymbolAddress(&pwpack, g_wpack);

    const int smem_gemm = 32 * GN * 4 + 32 * 32 * 8;                    // 73728
    const int smem_fuse = FICC * 6 * FSTR * 4 + FICC * 9 * 32 * 8;      // 89088
    const int smem_ap   = 96 * AP_TN * 4 + 1536 * 4;                    // 202752
    cudaFuncSetAttribute(gemm1x1_kernel, cudaFuncAttributeMaxDynamicSharedMemorySize, smem_gemm);
    cudaFuncSetAttribute(fuse3x3_kernel, cudaFuncAttributeMaxDynamicSharedMemorySize, smem_fuse);
    cudaFuncSetAttribute(applyattn_kernel, cudaFuncAttributeMaxDynamicSharedMemorySize, smem_ap);

    pack_kernel<<<(C2_ * 288 + 255) / 256, 256>>>(w_proj, w_pos);

    dim3 gg(NPIX / GN, C2_ / 32, B_);   // (32, 6, 8)

    // qv_ branch: 1x1 then depthwise
    gemm1x1_kernel<<<gg, 256, smem_gemm>>>(x, nullptr, nullptr, w_qv, (float*)pt, C2_, 96);
    dw3x3_kernel<<<dim3(NPIX / 256, C2_, B_), 256>>>((const float*)pt, w_qv_dw, (float*)pqv);
    // kv branch
    gemm1x1_kernel<<<gg, 256, smem_gemm>>>(y, nullptr, nullptr, w_kv, (float*)pt, C2_, 96);
    dw3x3_kernel<<<dim3(NPIX / 256, C2_, B_), 256>>>((const float*)pt, w_kv_dw, (float*)pkv);
    // v = fuse3x3(cat(v0, v_)) + bias
    fuse3x3_kernel<<<dim3(H_ / 4, C_ / 32, B_), 256, smem_fuse>>>(w_fuse, b_fuse);
    // q/k L2 norms
    norm_kernel<<<dim3(C_, B_, 2), 256>>>();
    // gram + softmax
    attn_kernel<<<dim3(HEADS_, B_), 256>>>(temp);
    // out = attn @ v
    applyattn_kernel<<<dim3(NPIX / AP_TN, B_), 256, smem_ap>>>();
    // final: w_proj @ att + w_pos @ [x; y]
    gemm1x1_kernel<<<gg, 256, smem_gemm>>>((const float*)patt, x, y,
                                           (const float*)pwpack, out, C2_, 288);
}

// round 5
// speedup vs baseline: 1.6645x; 1.0667x over previous
#include <cuda_runtime.h>
#include <math.h>
#include <stdint.h>

#define B_    8
#define C_    96
#define C2_   192
#define NPIX  16384
#define HEADS_ 6

typedef unsigned long long u64;

// ---------------- f32x2 helpers (small kernels) ----------------
__device__ __forceinline__ u64 pk2(float lo, float hi) {
    u64 r; asm("mov.b64 %0,{%1,%2};" : "=l"(r) : "f"(lo), "f"(hi)); return r;
}
__device__ __forceinline__ u64 fma2(u64 a, u64 b, u64 c) {
    u64 d; asm("fma.rn.f32x2 %0,%1,%2,%3;" : "=l"(d) : "l"(a), "l"(b), "l"(c)); return d;
}
__device__ __forceinline__ void unpk(u64 a, float& lo, float& hi) {
    asm("mov.b64 {%0,%1},%2;" : "=f"(lo), "=f"(hi) : "l"(a));
}
__device__ __forceinline__ float to_tf32(float f) {
    unsigned u; asm("cvt.rna.tf32.f32 %0, %1;" : "=r"(u) : "f"(f));
    return __uint_as_float(u);
}
__device__ __forceinline__ void mma8(float* c, const uint32_t* a, uint32_t b0, uint32_t b1) {
    asm volatile("mma.sync.aligned.m16n8k8.row.col.f32.tf32.tf32.f32 "
                 "{%0,%1,%2,%3}, {%4,%5,%6,%7}, {%8,%9}, {%0,%1,%2,%3};"
                 : "+f"(c[0]), "+f"(c[1]), "+f"(c[2]), "+f"(c[3])
                 : "r"(a[0]), "r"(a[1]), "r"(a[2]), "r"(a[3]), "r"(b0), "r"(b1));
}

// ---- device-global scratch ----
__device__ float g_t  [B_ * C2_ * NPIX];
__device__ float g_qv [B_ * C2_ * NPIX];
__device__ float g_kv [B_ * C2_ * NPIX];
__device__ float g_v  [B_ * C_  * NPIX];
__device__ float g_att[B_ * C_  * NPIX];
__device__ float g_rq [B_ * C_];
__device__ float g_rk [B_ * C_];
__device__ float g_attn[B_ * HEADS_ * 16 * 16];
__device__ float g_wq  [C2_ * 96];
__device__ float g_wk  [C2_ * 96];
__device__ float g_wpk [C2_ * 288];
__device__ float g_wft [9 * 96 * 192];

// ============== tf32 mma.sync conv/GEMM ==============
// out[b, oc, n] (+= taps) = W[oc, k] @ IN[k, n]
// CTA: 96 oc x 128 px (one image row), 6 warps (3m x 2n), warp tile 32x64.
// smem: A [96][40] (k-interleaved in first 32 cols), B [128][40]; double buffered.
// Stride 40 floats = 160B: 8B-aligned for LDS.64 everywhere (stride 33 trapped).
#define SASTR 40
#define SBSTR 40
#define ABUF  (96 * SASTR)              // 3840 floats
#define BBUF  (128 * SBSTR)             // 5120 floats
#define BUFSZ (ABUF + BBUF)             // 8960 floats
#define SMEM_MMA (2 * BUFSZ * 4)        // 71680 bytes

__device__ __forceinline__ int kp(int kin) {   // interleave within 8-k group
    return (kin & 24) + ((kin & 3) << 1) + ((kin >> 2) & 1);
}

__global__ __launch_bounds__(192, 2)
void mma_conv(const float* __restrict__ s0, const float* __restrict__ s1,
              const float* __restrict__ s2, const float* __restrict__ W,
              float* __restrict__ out, const float* __restrict__ bias,
              int K, int Mtot, int ntaps, int mode)
{
    extern __shared__ float sm[];
    const int tid = threadIdx.x;
    const int wid = tid >> 5, lane = tid & 31;
    const int mw = wid >> 1, nw = wid & 1;          // 3 x 2 warps
    const int r = lane >> 2, cl = lane & 3;
    const int b = blockIdx.z, octile = blockIdx.y;
    const int n0 = blockIdx.x * 128;
    const int py = n0 >> 7;

    float acc[2][8][4];
#pragma unroll
    for (int i = 0; i < 2; i++)
#pragma unroll
        for (int j = 0; j < 8; j++)
#pragma unroll
            for (int q = 0; q < 4; q++) acc[i][j][q] = 0.f;

    const int nchunks = K / 32;
    const int nsteps = ntaps * nchunks;

    auto stage = [&](int s, int buf) {
        float* sA = sm + buf * BUFSZ;
        float* sB = sA + ABUF;
        int t = (ntaps == 1) ? 0 : (s / nchunks);
        int kc = s - t * nchunks;
        // ---- A: 96 oc x 32 k (weights pre-rounded tf32)
        {
            const float* wb = (mode == 1)
                ? (W + (size_t)t * 96 * 192 + kc * 32)
                : (W + (size_t)octile * 96 * K + kc * 32);
            int wstr = (mode == 1) ? 192 : K;
            for (int i = tid; i < 96 * 32; i += 192) {
                int oc = i >> 5, kin = i & 31;
                sA[oc * SASTR + kp(kin)] = wb[(size_t)oc * wstr + kin];
            }
        }
        // ---- B: 128 px x 32 k (transpose + tf32 round + OOB zero for taps)
        {
            int dy = t / 3 - 1, dx = t % 3 - 1;
            int gy = py + dy;
            bool rowok = (mode != 1) || ((unsigned)gy < 128u);
            for (int i = tid; i < 128 * 32; i += 192) {
                int c = i >> 7, px = i & 127;
                int cg = kc * 32 + c;
                float v = 0.f;
                if (mode == 1) {
                    int gx = px + dx;
                    if (rowok && (unsigned)gx < 128u) {
                        const float* sp = (cg < 96)
                            ? (g_kv + ((size_t)b * C2_ + 96 + cg) * NPIX)
                            : (g_qv + ((size_t)b * C2_ + cg) * NPIX);
                        v = sp[gy * 128 + gx];
                    }
                } else {
                    const float* base = (cg < 96) ? s0 : (cg < 192) ? s1 : s2;
                    v = base[((size_t)b * 96 + (cg % 96)) * NPIX + n0 + px];
                }
                sB[px * SBSTR + kp(c)] = to_tf32(v);
            }
        }
    };

    stage(0, 0);
    __syncthreads();
    for (int s = 0; s < nsteps; s++) {
        int buf = s & 1;
        if (s + 1 < nsteps) stage(s + 1, buf ^ 1);
        const float* sA = sm + buf * BUFSZ;
        const float* sB = sA + ABUF;
#pragma unroll
        for (int ks = 0; ks < 4; ks++) {
            uint32_t af[2][4];
#pragma unroll
            for (int mt = 0; mt < 2; mt++) {
                int row = mw * 32 + mt * 16 + r;
                float2 lo = *(const float2*)(sA + row * SASTR + ks * 8 + cl * 2);
                float2 hi = *(const float2*)(sA + (row + 8) * SASTR + ks * 8 + cl * 2);
                af[mt][0] = __float_as_uint(lo.x);
                af[mt][2] = __float_as_uint(lo.y);
                af[mt][1] = __float_as_uint(hi.x);
                af[mt][3] = __float_as_uint(hi.y);
            }
#pragma unroll
            for (int nt = 0; nt < 8; nt++) {
                int px = nw * 64 + nt * 8 + r;
                float2 bb = *(const float2*)(sB + px * SBSTR + ks * 8 + cl * 2);
                uint32_t b0 = __float_as_uint(bb.x), b1 = __float_as_uint(bb.y);
                mma8(acc[0][nt], af[0], b0, b1);
                mma8(acc[1][nt], af[1], b0, b1);
            }
        }
        __syncthreads();
    }

    // ---- epilogue
    int ocb = octile * 96 + mw * 32;
#pragma unroll
    for (int mt = 0; mt < 2; mt++) {
        int oc = ocb + mt * 16 + r;
        float bv0 = bias ? bias[oc] : 0.f;
        float bv8 = bias ? bias[oc + 8] : 0.f;
        float* ob = out + ((size_t)b * Mtot + oc) * NPIX + n0 + nw * 64 + 2 * cl;
#pragma unroll
        for (int nt = 0; nt < 8; nt++) {
            float* op = ob + nt * 8;
            *(float2*)op = make_float2(acc[mt][nt][0] + bv0, acc[mt][nt][1] + bv0);
            *(float2*)(op + (size_t)8 * NPIX) =
                make_float2(acc[mt][nt][2] + bv8, acc[mt][nt][3] + bv8);
        }
    }
}

// ======================= weight pack kernels (tf32 round) =======================
__global__ void pack_a(const float* __restrict__ w, float* __restrict__ dst, int total)
{
    int idx = blockIdx.x * 256 + threadIdx.x;
    if (idx < total) dst[idx] = to_tf32(w[idx]);
}
__global__ void pack_final(const float* __restrict__ wp, const float* __restrict__ wpos,
                           float* __restrict__ dst)
{
    int idx = blockIdx.x * 256 + threadIdx.x;
    if (idx < C2_ * 288) {
        int oc = idx / 288, k = idx - oc * 288;
        float v = (k < 96) ? wp[(size_t)oc * 96 + k] : wpos[(size_t)oc * 192 + (k - 96)];
        dst[idx] = to_tf32(v);
    }
}
__global__ void pack_fuse(const float* __restrict__ wf, float* __restrict__ dst)
{
    int idx = blockIdx.x * 256 + threadIdx.x;   // [t][oc 96][ic 192]
    if (idx < 9 * 96 * 192) {
        int t = idx / (96 * 192);
        int rem = idx - t * (96 * 192);
        int oc = rem / 192, ic = rem - oc * 192;
        dst[idx] = to_tf32(wf[((size_t)oc * 192 + ic) * 9 + t]);
    }
}

// ======================= depthwise 3x3, pad 1 =======================
__global__ void dw3x3_kernel(const float* __restrict__ in, const float* __restrict__ wdw,
                             float* __restrict__ out)
{
    int b = blockIdx.z, c = blockIdx.y;
    int n = blockIdx.x * 256 + threadIdx.x;
    int yy = n >> 7, xx = n & 127;
    const float* ip = in + ((size_t)b * C2_ + c) * NPIX;
    const float* wp = wdw + c * 9;
    float acc = 0.f;
#pragma unroll
    for (int ky = 0; ky < 3; ky++) {
        int gy = yy + ky - 1;
        if ((unsigned)gy < 128u) {
#pragma unroll
            for (int kx = 0; kx < 3; kx++) {
                int gx = xx + kx - 1;
                if ((unsigned)gx < 128u) acc = fmaf(wp[ky * 3 + kx], ip[gy * 128 + gx], acc);
            }
        }
    }
    out[((size_t)b * C2_ + c) * NPIX + n] = acc;
}

// ======================= L2 norms of q, k rows =======================
__global__ void norm_kernel()
{
    __shared__ float red[256];
    int c = blockIdx.x, b = blockIdx.y, which = blockIdx.z;
    const float* src = (which ? g_kv : g_qv) + ((size_t)b * C2_ + c) * NPIX;
    float ss = 0.f;
    for (int n = threadIdx.x; n < NPIX; n += 256) { float v = src[n]; ss = fmaf(v, v, ss); }
    red[threadIdx.x] = ss;
    __syncthreads();
    for (int s = 128; s > 0; s >>= 1) {
        if (threadIdx.x < s) red[threadIdx.x] += red[threadIdx.x + s];
        __syncthreads();
    }
    if (threadIdx.x == 0) {
        float inv = 1.f / fmaxf(sqrtf(red[0]), 1e-12f);
        (which ? g_rk : g_rq)[b * C_ + c] = inv;
    }
}

// =============== 16x16 gram + temperature + softmax per (b,h) ===============
#define GR_NC 256
__global__ void attn_kernel(const float* __restrict__ temp)
{
    __shared__ float sq[16][GR_NC + 2];
    __shared__ float sk[16][GR_NC + 2];
    __shared__ float gm[16][17];
    int h = blockIdx.x, b = blockIdx.y;
    int tid = threadIdx.x;
    int i = tid >> 4, j = tid & 15;
    const float* qb = g_qv + ((size_t)b * C2_ + h * 16) * NPIX;
    const float* kb = g_kv + ((size_t)b * C2_ + h * 16) * NPIX;
    float acc = 0.f;
    for (int n0 = 0; n0 < NPIX; n0 += GR_NC) {
        for (int idx = tid; idx < 16 * GR_NC; idx += 256) {
            int c = idx >> 8, nn = idx & (GR_NC - 1);
            sq[c][nn] = qb[(size_t)c * NPIX + n0 + nn];
            sk[c][nn] = kb[(size_t)c * NPIX + n0 + nn];
        }
        __syncthreads();
#pragma unroll 4
        for (int nn = 0; nn < GR_NC; nn++) acc = fmaf(sq[i][nn], sk[j][nn], acc);
        __syncthreads();
    }
    gm[i][j] = acc * g_rq[b * C_ + h * 16 + i] * g_rk[b * C_ + h * 16 + j] * temp[h];
    __syncthreads();
    if (tid < 16) {
        int ii = tid;
        float m = -1e30f;
        for (int jj = 0; jj < 16; jj++) m = fmaxf(m, gm[ii][jj]);
        float e[16], ssum = 0.f;
        for (int jj = 0; jj < 16; jj++) { e[jj] = expf(gm[ii][jj] - m); ssum += e[jj]; }
        float inv = 1.f / ssum;
        for (int jj = 0; jj < 16; jj++)
            g_attn[(((size_t)b * HEADS_ + h) * 16 + ii) * 16 + jj] = e[jj] * inv;
    }
}

// ================== out[b,c,n] = sum_j attn[b,h,i,j] * v[b,h*16+j,n] ==================
#define AP_TN 512
__global__ __launch_bounds__(256, 1)
void applyattn_kernel()
{
    extern __shared__ float sm[];
    float* sv = sm;
    float* sa = sm + 96 * AP_TN;
    int tid = threadIdx.x;
    int b = blockIdx.y;
    int n0 = blockIdx.x * AP_TN;
    for (int idx = tid; idx < 96 * AP_TN; idx += 256) {
        int c = idx >> 9, pp = idx & (AP_TN - 1);
        sv[idx] = g_v[((size_t)b * C_ + c) * NPIX + n0 + pp];
    }
    for (int idx = tid; idx < 1536; idx += 256) sa[idx] = g_attn[(size_t)b * 1536 + idx];
    __syncthreads();
    const u64* svp = (const u64*)sv;
    for (int c = 0; c < C_; c++) {
        int hh = c >> 4, ii = c & 15;
        u64 acc = 0ull;
        const float* ar = sa + (hh * 16 + ii) * 16;
#pragma unroll
        for (int jj = 0; jj < 16; jj++) {
            float a = ar[jj];
            acc = fma2(pk2(a, a), svp[(hh * 16 + jj) * (AP_TN / 2) + tid], acc);
        }
        float lo, hi; unpk(acc, lo, hi);
        *(float2*)(g_att + ((size_t)b * C_ + c) * NPIX + n0 + 2 * tid) = make_float2(lo, hi);
    }
}

extern "C" void kernel_launch(void* const* d_in, const int* in_sizes, int n_in,
                              void* d_out, int out_size)
{
    const float* x        = (const float*)d_in[0];
    const float* y        = (const float*)d_in[1];
    const float* w_pos    = (const float*)d_in[2];
    const float* w_qv     = (const float*)d_in[3];
    const float* w_qv_dw  = (const float*)d_in[4];
    const float* w_kv     = (const float*)d_in[5];
    const float* w_kv_dw  = (const float*)d_in[6];
    const float* w_proj   = (const float*)d_in[7];
    const float* w_fuse   = (const float*)d_in[8];
    const float* b_fuse   = (const float*)d_in[9];
    const float* temp     = (const float*)d_in[10];
    float* out = (float*)d_out;

    void *pt, *pqv, *pkv, *patt, *pwq, *pwk, *pwpk, *pwft, *pv;
    cudaGetSymbolAddress(&pt, g_t);
    cudaGetSymbolAddress(&pqv, g_qv);
    cudaGetSymbolAddress(&pkv, g_kv);
    cudaGetSymbolAddress(&patt, g_att);
    cudaGetSymbolAddress(&pwq, g_wq);
    cudaGetSymbolAddress(&pwk, g_wk);
    cudaGetSymbolAddress(&pwpk, g_wpk);
    cudaGetSymbolAddress(&pwft, g_wft);
    cudaGetSymbolAddress(&pv, g_v);

    const int smem_ap = 96 * AP_TN * 4 + 1536 * 4;
    cudaFuncSetAttribute(mma_conv, cudaFuncAttributeMaxDynamicSharedMemorySize, SMEM_MMA);
    cudaFuncSetAttribute(applyattn_kernel, cudaFuncAttributeMaxDynamicSharedMemorySize, smem_ap);

    // weight packing (tf32-rounded)
    pack_a<<<(C2_ * 96 + 255) / 256, 256>>>(w_qv, (float*)pwq, C2_ * 96);
    pack_a<<<(C2_ * 96 + 255) / 256, 256>>>(w_kv, (float*)pwk, C2_ * 96);
    pack_final<<<(C2_ * 288 + 255) / 256, 256>>>(w_proj, w_pos, (float*)pwpk);
    pack_fuse<<<(9 * 96 * 192 + 255) / 256, 256>>>(w_fuse, (float*)pwft);

    // qv branch
    mma_conv<<<dim3(128, 2, B_), 192, SMEM_MMA>>>(
        x, nullptr, nullptr, (const float*)pwq, (float*)pt, nullptr, 96, 192, 1, 0);
    dw3x3_kernel<<<dim3(NPIX / 256, C2_, B_), 256>>>((const float*)pt, w_qv_dw, (float*)pqv);
    // kv branch
    mma_conv<<<dim3(128, 2, B_), 192, SMEM_MMA>>>(
        y, nullptr, nullptr, (const float*)pwk, (float*)pt, nullptr, 96, 192, 1, 0);
    dw3x3_kernel<<<dim3(NPIX / 256, C2_, B_), 256>>>((const float*)pt, w_kv_dw, (float*)pkv);
    // v = fuse3x3(cat(v0, v_)) + bias   (9 shifted GEMM taps)
    mma_conv<<<dim3(128, 1, B_), 192, SMEM_MMA>>>(
        nullptr, nullptr, nullptr, (const float*)pwft, (float*)pv, b_fuse, 192, 96, 9, 1);
    // attention
    norm_kernel<<<dim3(C_, B_, 2), 256>>>();
    attn_kernel<<<dim3(HEADS_, B_), 256>>>(temp);
    applyattn_kernel<<<dim3(NPIX / AP_TN, B_), 256, smem_ap>>>();
    // final: w_proj @ att + w_pos @ [x; y]
    mma_conv<<<dim3(128, 2, B_), 192, SMEM_MMA>>>(
        (const float*)patt, x, y, (const float*)pwpk, out, nullptr, 288, 192, 1, 0);
}

// round 6
// speedup vs baseline: 2.5638x; 1.5403x over previous
#include <cuda_runtime.h>
#include <math.h>
#include <stdint.h>

#define B_    8
#define C_    96
#define C2_   192
#define NPIX  16384
#define HEADS_ 6

typedef unsigned long long u64;

__device__ __forceinline__ u64 pk2(float lo, float hi) {
    u64 r; asm("mov.b64 %0,{%1,%2};" : "=l"(r) : "f"(lo), "f"(hi)); return r;
}
__device__ __forceinline__ u64 fma2(u64 a, u64 b, u64 c) {
    u64 d; asm("fma.rn.f32x2 %0,%1,%2,%3;" : "=l"(d) : "l"(a), "l"(b), "l"(c)); return d;
}
__device__ __forceinline__ void unpk(u64 a, float& lo, float& hi) {
    asm("mov.b64 {%0,%1},%2;" : "=f"(lo), "=f"(hi) : "l"(a));
}
__device__ __forceinline__ float to_tf32(float f) {
    unsigned u; asm("cvt.rna.tf32.f32 %0, %1;" : "=r"(u) : "f"(f));
    return __uint_as_float(u);
}
__device__ __forceinline__ void mma8(float* c, const uint32_t* a, uint32_t b0, uint32_t b1) {
    asm volatile("mma.sync.aligned.m16n8k8.row.col.f32.tf32.tf32.f32 "
                 "{%0,%1,%2,%3}, {%4,%5,%6,%7}, {%8,%9}, {%0,%1,%2,%3};"
                 : "+f"(c[0]), "+f"(c[1]), "+f"(c[2]), "+f"(c[3])
                 : "r"(a[0]), "r"(a[1]), "r"(a[2]), "r"(a[3]), "r"(b0), "r"(b1));
}

// ---- device-global scratch ----
__device__ float g_t  [B_ * C2_ * NPIX];
__device__ float g_qv [B_ * C2_ * NPIX];
__device__ float g_kv [B_ * C2_ * NPIX];
__device__ float g_v  [B_ * C_  * NPIX];
__device__ float g_att[B_ * C_  * NPIX];
__device__ float g_rq [B_ * C_];
__device__ float g_rk [B_ * C_];
__device__ float g_attn[B_ * HEADS_ * 16 * 16];
__device__ float g_wq  [C2_ * 96];
__device__ float g_wk  [C2_ * 96];
__device__ float g_wpk [C2_ * 288];
__device__ float g_wft [9 * 96 * 192];

__device__ __forceinline__ int kp(int kin) {   // interleave within 8-k group
    return (kin & 24) + ((kin & 3) << 1) + ((kin >> 2) & 1);
}

// ============== tf32 mma.sync 1x1 GEMM, M=192 in one CTA ==============
// CTA: 192 oc x 128 px, 12 warps (6m x 2n), warp tile 32x64.
#define GASTR 40
#define GABUF  (192 * GASTR)            // 7680 floats
#define GBBUF  (128 * GASTR)            // 5120 floats
#define GBUFSZ (GABUF + GBBUF)          // 12800 floats
#define SMEM_G (2 * GBUFSZ * 4)         // 102400 bytes

__global__ __launch_bounds__(384, 1)
void mma_gemm(const float* __restrict__ s0, const float* __restrict__ s1,
              const float* __restrict__ s2, const float* __restrict__ W,
              float* __restrict__ out, int K)
{
    extern __shared__ float sm[];
    const int tid = threadIdx.x;
    const int wid = tid >> 5, lane = tid & 31;
    const int mw = wid >> 1, nw = wid & 1;          // 6 x 2 warps
    const int r = lane >> 2, cl = lane & 3;
    const int b = blockIdx.y;
    const int n0 = blockIdx.x * 128;

    float acc[2][8][4];
#pragma unroll
    for (int i = 0; i < 2; i++)
#pragma unroll
        for (int j = 0; j < 8; j++)
#pragma unroll
            for (int q = 0; q < 4; q++) acc[i][j][q] = 0.f;

    const int nsteps = K / 32;

    auto stage = [&](int kc, int buf) {
        float* sA = sm + buf * GBUFSZ;
        float* sB = sA + GABUF;
        const float* wb = W + kc * 32;
        for (int i = tid; i < 192 * 32; i += 384) {
            int oc = i >> 5, kin = i & 31;
            sA[oc * GASTR + kp(kin)] = wb[(size_t)oc * K + kin];
        }
        for (int i = tid; i < 128 * 32; i += 384) {
            int c = i >> 7, px = i & 127;
            int cg = kc * 32 + c;
            const float* base = (cg < 96) ? s0 : (cg < 192) ? s1 : s2;
            float v = base[((size_t)b * 96 + (cg % 96)) * NPIX + n0 + px];
            sB[px * GASTR + kp(c)] = to_tf32(v);
        }
    };

    stage(0, 0);
    __syncthreads();
    for (int s = 0; s < nsteps; s++) {
        int buf = s & 1;
        if (s + 1 < nsteps) stage(s + 1, buf ^ 1);
        const float* sA = sm + buf * GBUFSZ;
        const float* sB = sA + GABUF;
#pragma unroll
        for (int ks = 0; ks < 4; ks++) {
            uint32_t af[2][4];
#pragma unroll
            for (int mt = 0; mt < 2; mt++) {
                int row = mw * 32 + mt * 16 + r;
                float2 lo = *(const float2*)(sA + row * GASTR + ks * 8 + cl * 2);
                float2 hi = *(const float2*)(sA + (row + 8) * GASTR + ks * 8 + cl * 2);
                af[mt][0] = __float_as_uint(lo.x);
                af[mt][2] = __float_as_uint(lo.y);
                af[mt][1] = __float_as_uint(hi.x);
                af[mt][3] = __float_as_uint(hi.y);
            }
#pragma unroll
            for (int nt = 0; nt < 8; nt++) {
                int px = nw * 64 + nt * 8 + r;
                float2 bb = *(const float2*)(sB + px * GASTR + ks * 8 + cl * 2);
                uint32_t b0 = __float_as_uint(bb.x), b1 = __float_as_uint(bb.y);
                mma8(acc[0][nt], af[0], b0, b1);
                mma8(acc[1][nt], af[1], b0, b1);
            }
        }
        __syncthreads();
    }

    int ocb = mw * 32;
#pragma unroll
    for (int mt = 0; mt < 2; mt++) {
        int oc = ocb + mt * 16 + r;
        float* ob = out + ((size_t)b * 192 + oc) * NPIX + n0 + nw * 64 + 2 * cl;
#pragma unroll
        for (int nt = 0; nt < 8; nt++) {
            float* op = ob + nt * 8;
            *(float2*)op = make_float2(acc[mt][nt][0], acc[mt][nt][1]);
            *(float2*)(op + (size_t)8 * NPIX) = make_float2(acc[mt][nt][2], acc[mt][nt][3]);
        }
    }
}

// ============== fuse conv 3x3 (192->96): halo-resident taps ==============
// CTA: 96 oc x 256 px (2 out rows). Input chunk (32 ic x 4 rows x 132 cols)
// staged ONCE, 9 taps run from smem with shifted views. 12 warps (3m x 4n).
#define FICSTR 536                       // padded per-ic stride (words)
#define FROWSTR 132
#define FIN_SZ (32 * FICSTR)             // 17152 floats
#define FW_SZ  (96 * 40)                 // 3840 floats
#define SMEM_F ((FIN_SZ + 2 * FW_SZ) * 4)  // 99328 bytes

__global__ __launch_bounds__(384, 1)
void fuse_mma(const float* __restrict__ Wt, const float* __restrict__ bias)
{
    extern __shared__ float sm[];
    float* sIn = sm;
    float* sW  = sm + FIN_SZ;
    const int tid = threadIdx.x;
    const int wid = tid >> 5, lane = tid & 31;
    const int mw = wid >> 2, nw = wid & 3;          // 3 x 4 warps
    const int r = lane >> 2, cl = lane & 3;
    const int b = blockIdx.y;
    const int r0 = blockIdx.x * 2;
    const int pr = nw >> 1;                          // out row within tile
    const int xh = (nw & 1) * 64;                    // col half base

    float acc[2][8][4];
#pragma unroll
    for (int i = 0; i < 2; i++)
#pragma unroll
        for (int j = 0; j < 8; j++)
#pragma unroll
            for (int q = 0; q < 4; q++) acc[i][j][q] = 0.f;

    auto stageW = [&](int kc, int t, int buf) {
        float* dst = sW + buf * FW_SZ;
        const float* wb = Wt + (size_t)t * 96 * 192 + kc * 32;
        for (int i = tid; i < 96 * 32; i += 384) {
            int oc = i >> 5, ic = i & 31;
            dst[oc * 40 + kp(ic)] = wb[(size_t)oc * 192 + ic];
        }
    };

    for (int kc = 0; kc < 6; kc++) {
        __syncthreads();
        // ---- stage input chunk: 32 ic x 4 rows x 130 cols (haloed, zero-filled)
        {
            int icg0 = kc * 32;
            const float* srcbase = (icg0 < 96)
                ? (g_kv + ((size_t)b * C2_ + 96 + icg0) * NPIX)
                : (g_qv + ((size_t)b * C2_ + icg0) * NPIX);
            for (int seg = wid; seg < 128; seg += 12) {
                int c = seg >> 2, rr = seg & 3;
                int gy = r0 + rr - 1;
                float* drow = sIn + c * FICSTR + rr * FROWSTR;
                const float* srow = srcbase + (size_t)c * NPIX + gy * 128;
                bool rowok = (unsigned)gy < 128u;
#pragma unroll
                for (int cc = lane; cc < 132; cc += 32) {
                    int gx = cc - 1;
                    float v = (rowok && (unsigned)gx < 128u) ? srow[gx] : 0.f;
                    drow[cc] = to_tf32(v);
                }
            }
        }
        stageW(kc, 0, 0);
        __syncthreads();

        for (int t = 0; t < 9; t++) {
            int buf = t & 1;
            if (t + 1 < 9) stageW(kc, t + 1, buf ^ 1);
            int dy = t / 3 - 1, dx = t - (t / 3) * 3 - 1;
            const float* sA = sW + buf * FW_SZ;
            const float* bbase = sIn + (pr + dy + 1) * FROWSTR + xh + dx + 1 + r;
#pragma unroll
            for (int ks = 0; ks < 4; ks++) {
                uint32_t af[2][4];
#pragma unroll
                for (int mt = 0; mt < 2; mt++) {
                    int row = mw * 32 + mt * 16 + r;
                    float2 lo = *(const float2*)(sA + row * 40 + ks * 8 + cl * 2);
                    float2 hi = *(const float2*)(sA + (row + 8) * 40 + ks * 8 + cl * 2);
                    af[mt][0] = __float_as_uint(lo.x);
                    af[mt][2] = __float_as_uint(lo.y);
                    af[mt][1] = __float_as_uint(hi.x);
                    af[mt][3] = __float_as_uint(hi.y);
                }
                const float* b0p = bbase + (ks * 8 + cl) * FICSTR;
                const float* b1p = b0p + 4 * FICSTR;
#pragma unroll
                for (int nt = 0; nt < 8; nt++) {
                    uint32_t b0 = __float_as_uint(b0p[nt * 8]);
                    uint32_t b1 = __float_as_uint(b1p[nt * 8]);
                    mma8(acc[0][nt], af[0], b0, b1);
                    mma8(acc[1][nt], af[1], b0, b1);
                }
            }
            __syncthreads();
        }
    }

    // ---- epilogue
#pragma unroll
    for (int mt = 0; mt < 2; mt++) {
        int oc = mw * 32 + mt * 16 + r;
        float bv0 = bias[oc];
        float bv8 = bias[oc + 8];
        float* ob = g_v + ((size_t)b * C_ + oc) * NPIX + (r0 + pr) * 128 + xh + 2 * cl;
#pragma unroll
        for (int nt = 0; nt < 8; nt++) {
            float* op = ob + nt * 8;
            *(float2*)op = make_float2(acc[mt][nt][0] + bv0, acc[mt][nt][1] + bv0);
            *(float2*)(op + (size_t)8 * NPIX) =
                make_float2(acc[mt][nt][2] + bv8, acc[mt][nt][3] + bv8);
        }
    }
}

// ======================= weight pack kernels (tf32 round) =======================
__global__ void pack_a(const float* __restrict__ w, float* __restrict__ dst, int total)
{
    int idx = blockIdx.x * 256 + threadIdx.x;
    if (idx < total) dst[idx] = to_tf32(w[idx]);
}
__global__ void pack_final(const float* __restrict__ wp, const float* __restrict__ wpos,
                           float* __restrict__ dst)
{
    int idx = blockIdx.x * 256 + threadIdx.x;
    if (idx < C2_ * 288) {
        int oc = idx / 288, k = idx - oc * 288;
        float v = (k < 96) ? wp[(size_t)oc * 96 + k] : wpos[(size_t)oc * 192 + (k - 96)];
        dst[idx] = to_tf32(v);
    }
}
__global__ void pack_fuse(const float* __restrict__ wf, float* __restrict__ dst)
{
    int idx = blockIdx.x * 256 + threadIdx.x;   // [t][oc 96][ic 192]
    if (idx < 9 * 96 * 192) {
        int t = idx / (96 * 192);
        int rem = idx - t * (96 * 192);
        int oc = rem / 192, ic = rem - oc * 192;
        dst[idx] = to_tf32(wf[((size_t)oc * 192 + ic) * 9 + t]);
    }
}

// ======================= depthwise 3x3, pad 1 =======================
__global__ void dw3x3_kernel(const float* __restrict__ in, const float* __restrict__ wdw,
                             float* __restrict__ out)
{
    int b = blockIdx.z, c = blockIdx.y;
    int n = blockIdx.x * 256 + threadIdx.x;
    int yy = n >> 7, xx = n & 127;
    const float* ip = in + ((size_t)b * C2_ + c) * NPIX;
    const float* wp = wdw + c * 9;
    float acc = 0.f;
#pragma unroll
    for (int ky = 0; ky < 3; ky++) {
        int gy = yy + ky - 1;
        if ((unsigned)gy < 128u) {
#pragma unroll
            for (int kx = 0; kx < 3; kx++) {
                int gx = xx + kx - 1;
                if ((unsigned)gx < 128u) acc = fmaf(wp[ky * 3 + kx], ip[gy * 128 + gx], acc);
            }
        }
    }
    out[((size_t)b * C2_ + c) * NPIX + n] = acc;
}

// ======================= L2 norms of q, k rows =======================
__global__ void norm_kernel()
{
    __shared__ float red[256];
    int c = blockIdx.x, b = blockIdx.y, which = blockIdx.z;
    const float* src = (which ? g_kv : g_qv) + ((size_t)b * C2_ + c) * NPIX;
    float ss = 0.f;
    for (int n = threadIdx.x; n < NPIX; n += 256) { float v = src[n]; ss = fmaf(v, v, ss); }
    red[threadIdx.x] = ss;
    __syncthreads();
    for (int s = 128; s > 0; s >>= 1) {
        if (threadIdx.x < s) red[threadIdx.x] += red[threadIdx.x + s];
        __syncthreads();
    }
    if (threadIdx.x == 0) {
        float inv = 1.f / fmaxf(sqrtf(red[0]), 1e-12f);
        (which ? g_rk : g_rq)[b * C_ + c] = inv;
    }
}

// =============== 16x16 gram + temperature + softmax per (b,h) ===============
#define GR_NC 256
__global__ void attn_kernel(const float* __restrict__ temp)
{
    __shared__ float sq[16][GR_NC + 2];
    __shared__ float sk[16][GR_NC + 2];
    __shared__ float gm[16][17];
    int h = blockIdx.x, b = blockIdx.y;
    int tid = threadIdx.x;
    int i = tid >> 4, j = tid & 15;
    const float* qb = g_qv + ((size_t)b * C2_ + h * 16) * NPIX;
    const float* kb = g_kv + ((size_t)b * C2_ + h * 16) * NPIX;
    float acc = 0.f;
    for (int n0 = 0; n0 < NPIX; n0 += GR_NC) {
        for (int idx = tid; idx < 16 * GR_NC; idx += 256) {
            int c = idx >> 8, nn = idx & (GR_NC - 1);
            sq[c][nn] = qb[(size_t)c * NPIX + n0 + nn];
            sk[c][nn] = kb[(size_t)c * NPIX + n0 + nn];
        }
        __syncthreads();
#pragma unroll 4
        for (int nn = 0; nn < GR_NC; nn++) acc = fmaf(sq[i][nn], sk[j][nn], acc);
        __syncthreads();
    }
    gm[i][j] = acc * g_rq[b * C_ + h * 16 + i] * g_rk[b * C_ + h * 16 + j] * temp[h];
    __syncthreads();
    if (tid < 16) {
        int ii = tid;
        float m = -1e30f;
        for (int jj = 0; jj < 16; jj++) m = fmaxf(m, gm[ii][jj]);
        float e[16], ssum = 0.f;
        for (int jj = 0; jj < 16; jj++) { e[jj] = expf(gm[ii][jj] - m); ssum += e[jj]; }
        float inv = 1.f / ssum;
        for (int jj = 0; jj < 16; jj++)
            g_attn[(((size_t)b * HEADS_ + h) * 16 + ii) * 16 + jj] = e[jj] * inv;
    }
}

// ================== out[b,c,n] = sum_j attn[b,h,i,j] * v[b,h*16+j,n] ==================
#define AP_TN 512
__global__ __launch_bounds__(256, 1)
void applyattn_kernel()
{
    extern __shared__ float sm[];
    float* sv = sm;
    float* sa = sm + 96 * AP_TN;
    int tid = threadIdx.x;
    int b = blockIdx.y;
    int n0 = blockIdx.x * AP_TN;
    for (int idx = tid; idx < 96 * AP_TN; idx += 256) {
        int c = idx >> 9, pp = idx & (AP_TN - 1);
        sv[idx] = g_v[((size_t)b * C_ + c) * NPIX + n0 + pp];
    }
    for (int idx = tid; idx < 1536; idx += 256) sa[idx] = g_attn[(size_t)b * 1536 + idx];
    __syncthreads();
    const u64* svp = (const u64*)sv;
    for (int c = 0; c < C_; c++) {
        int hh = c >> 4, ii = c & 15;
        u64 acc = 0ull;
        const float* ar = sa + (hh * 16 + ii) * 16;
#pragma unroll
        for (int jj = 0; jj < 16; jj++) {
            float a = ar[jj];
            acc = fma2(pk2(a, a), svp[(hh * 16 + jj) * (AP_TN / 2) + tid], acc);
        }
        float lo, hi; unpk(acc, lo, hi);
        *(float2*)(g_att + ((size_t)b * C_ + c) * NPIX + n0 + 2 * tid) = make_float2(lo, hi);
    }
}

extern "C" void kernel_launch(void* const* d_in, const int* in_sizes, int n_in,
                              void* d_out, int out_size)
{
    const float* x        = (const float*)d_in[0];
    const float* y        = (const float*)d_in[1];
    const float* w_pos    = (const float*)d_in[2];
    const float* w_qv     = (const float*)d_in[3];
    const float* w_qv_dw  = (const float*)d_in[4];
    const float* w_kv     = (const float*)d_in[5];
    const float* w_kv_dw  = (const float*)d_in[6];
    const float* w_proj   = (const float*)d_in[7];
    const float* w_fuse   = (const float*)d_in[8];
    const float* b_fuse   = (const float*)d_in[9];
    const float* temp     = (const float*)d_in[10];
    float* out = (float*)d_out;

    void *pt, *pqv, *pkv, *patt, *pwq, *pwk, *pwpk, *pwft;
    cudaGetSymbolAddress(&pt, g_t);
    cudaGetSymbolAddress(&pqv, g_qv);
    cudaGetSymbolAddress(&pkv, g_kv);
    cudaGetSymbolAddress(&patt, g_att);
    cudaGetSymbolAddress(&pwq, g_wq);
    cudaGetSymbolAddress(&pwk, g_wk);
    cudaGetSymbolAddress(&pwpk, g_wpk);
    cudaGetSymbolAddress(&pwft, g_wft);

    const int smem_ap = 96 * AP_TN * 4 + 1536 * 4;
    cudaFuncSetAttribute(mma_gemm, cudaFuncAttributeMaxDynamicSharedMemorySize, SMEM_G);
    cudaFuncSetAttribute(fuse_mma, cudaFuncAttributeMaxDynamicSharedMemorySize, SMEM_F);
    cudaFuncSetAttribute(applyattn_kernel, cudaFuncAttributeMaxDynamicSharedMemorySize, smem_ap);

    // weight packing (tf32-rounded)
    pack_a<<<(C2_ * 96 + 255) / 256, 256>>>(w_qv, (float*)pwq, C2_ * 96);
    pack_a<<<(C2_ * 96 + 255) / 256, 256>>>(w_kv, (float*)pwk, C2_ * 96);
    pack_final<<<(C2_ * 288 + 255) / 256, 256>>>(w_proj, w_pos, (float*)pwpk);
    pack_fuse<<<(9 * 96 * 192 + 255) / 256, 256>>>(w_fuse, (float*)pwft);

    // qv branch
    mma_gemm<<<dim3(128, B_), 384, SMEM_G>>>(
        x, nullptr, nullptr, (const float*)pwq, (float*)pt, 96);
    dw3x3_kernel<<<dim3(NPIX / 256, C2_, B_), 256>>>((const float*)pt, w_qv_dw, (float*)pqv);
    // kv branch
    mma_gemm<<<dim3(128, B_), 384, SMEM_G>>>(
        y, nullptr, nullptr, (const float*)pwk, (float*)pt, 96);
    dw3x3_kernel<<<dim3(NPIX / 256, C2_, B_), 256>>>((const float*)pt, w_kv_dw, (float*)pkv);
    // v = fuse3x3(cat(v0, v_)) + bias — halo-resident 9-tap MMA
    fuse_mma<<<dim3(64, B_), 384, SMEM_F>>>((const float*)pwft, b_fuse);
    // attention
    norm_kernel<<<dim3(C_, B_, 2), 256>>>();
    attn_kernel<<<dim3(HEADS_, B_), 256>>>(temp);
    applyattn_kernel<<<dim3(NPIX / AP_TN, B_), 256, smem_ap>>>();
    // final: w_proj @ att + w_pos @ [x; y]
    mma_gemm<<<dim3(128, B_), 384, SMEM_G>>>(
        (const float*)patt, x, y, (const float*)pwpk, out, 288);
}